// round 2
// baseline (speedup 1.0000x reference)
#include <cuda_runtime.h>
#include <cstdint>

#define BB 8
#define NN 2048
#define FIN 128
#define FOUT 64

// ---- scratch (static device allocations are allowed) ----
__device__ float    g_h[BB * NN * FOUT];          // 4 MB
__device__ float    g_f1[BB * NN];
__device__ float    g_f2[BB * NN];
__device__ unsigned g_adj[BB * NN * (NN / 32)];   // 4 MB bitmask

// ---------------------------------------------------------------------------
// packed f32x2 helpers (Blackwell FFMA2)
// ---------------------------------------------------------------------------
__device__ __forceinline__ unsigned long long fma2(unsigned long long a,
                                                   unsigned long long b,
                                                   unsigned long long c) {
    unsigned long long d;
    asm("fma.rn.f32x2 %0, %1, %2, %3;" : "=l"(d) : "l"(a), "l"(b), "l"(c));
    return d;
}

// ---------------------------------------------------------------------------
// Kernel A: h = x @ W, f1 = h @ a[:64], f2 = h @ a[64:]
// 256 threads, 64 rows/block in two 32-row halves. Warp computes 4 rows per
// half; lane owns feature pair (2*lane, 2*lane+1) -> shuffle reduce for f1/f2.
// ---------------------------------------------------------------------------
__global__ __launch_bounds__(256) void k_proj(const float* __restrict__ x,
                                              const float* __restrict__ W,
                                              const float* __restrict__ a) {
    __shared__ float Ws[FIN * FOUT];   // 32 KB
    __shared__ float xs[32][FIN];      // 16 KB
    const int tid  = threadIdx.x;
    const int lane = tid & 31;
    const int warp = tid >> 5;

    // stage W (coalesced float4)
    {
        const float4* Wsrc = (const float4*)W;
        float4*       Wdst = (float4*)Ws;
#pragma unroll
        for (int c = 0; c < 8; ++c) Wdst[tid + 256 * c] = Wsrc[tid + 256 * c];
    }
    const float2 av1 = *(const float2*)(a + 2 * lane);
    const float2 av2 = *(const float2*)(a + FOUT + 2 * lane);

    const int row0 = blockIdx.x * 64;
    for (int half = 0; half < 2; ++half) {
        __syncthreads();
        {
            const float4* src = (const float4*)(x + (size_t)(row0 + half * 32) * FIN);
            float4*       dst = (float4*)xs;
#pragma unroll
            for (int c = 0; c < 4; ++c) dst[tid + 256 * c] = src[tid + 256 * c];
        }
        __syncthreads();

#pragma unroll
        for (int t = 0; t < 4; ++t) {
            const int rl  = warp * 4 + t;            // 0..31
            const int row = row0 + half * 32 + rl;
            float acc0 = 0.f, acc1 = 0.f;
#pragma unroll
            for (int k = 0; k < FIN; ++k) {
                const float  xv = xs[rl][k];
                const float2 wv = *(const float2*)(Ws + k * FOUT + 2 * lane);
                acc0 = fmaf(xv, wv.x, acc0);
                acc1 = fmaf(xv, wv.y, acc1);
            }
            *(float2*)(g_h + (size_t)row * FOUT + 2 * lane) = make_float2(acc0, acc1);

            float p1 = acc0 * av1.x + acc1 * av1.y;
            float p2 = acc0 * av2.x + acc1 * av2.y;
#pragma unroll
            for (int d = 16; d; d >>= 1) {
                p1 += __shfl_xor_sync(0xffffffffu, p1, d);
                p2 += __shfl_xor_sync(0xffffffffu, p2, d);
            }
            if (lane == 0) { g_f1[row] = p1; g_f2[row] = p2; }
        }
    }
}

// ---------------------------------------------------------------------------
// Kernel B: pack adj (int32, 134 MB) -> bitmask (4.2 MB). Memory-bound.
// ---------------------------------------------------------------------------
__global__ __launch_bounds__(256) void k_pack(const int* __restrict__ adj) {
    const int gwarp = (int)((blockIdx.x * blockDim.x + threadIdx.x) >> 5);
    const int lane  = threadIdx.x & 31;
    const size_t e0 = (size_t)gwarp * 128;
#pragma unroll
    for (int c = 0; c < 4; ++c) {
        const int v = adj[e0 + c * 32 + lane];
        const unsigned m = __ballot_sync(0xffffffffu, v > 0);
        if (lane == 0) g_adj[gwarp * 4 + c] = m;
    }
}

// ---------------------------------------------------------------------------
// Kernel C: fused masked attention + PV + ELU.
// Grid (NN/64, BB); block 256 = 64 rows x 4 feature quarters (16 f each).
// Per 32-j tile: phase A computes w_ij once per (i,j) into smem + stages h;
// phase B is dense FFMA2 (8 per j per thread) with broadcast h reads.
// Each thread owns disjoint features -> no reduction epilogue.
// ---------------------------------------------------------------------------
#define JT 32
#define NTILE (NN / JT)     // 64

__global__ void __launch_bounds__(256, 4)
k_attn(float* __restrict__ out) {
    __shared__ float               f2_s[NN];                 // 8 KB
    __shared__ __align__(16) float w_s[JT * 64];             // [j][r] 8 KB
    __shared__ __align__(16) float h_s[JT * FOUT];           // [j][f] 8 KB

    const int tid = threadIdx.x;
    const int r   = tid & 63;          // row within block
    const int q   = tid >> 6;          // feature quarter 0..3
    const int b   = blockIdx.y;
    const int i   = blockIdx.x * 64 + r;

    const float* f2b = g_f2 + b * NN;
    for (int l = tid; l < NN; l += 256) f2_s[l] = f2b[l];

    const float     f1i  = g_f1[b * NN + i];
    const unsigned* arow = g_adj + (size_t)(b * NN + i) * (NN / 32);
    const float*    hb   = g_h + (size_t)b * NN * FOUT;

    unsigned long long acc[8];
#pragma unroll
    for (int k = 0; k < 8; ++k) acc[k] = 0ull;
    float denom = 0.f;

    __syncthreads();

    for (int tile = 0; tile < NTILE; ++tile) {
        // ---- phase A: stage h tile + compute scores once per (i,j) ----
        {
            const float4* hsrc = (const float4*)(hb + (size_t)tile * JT * FOUT);
            float4*       hdst = (float4*)h_s;
            hdst[tid]       = hsrc[tid];
            hdst[tid + 256] = hsrc[tid + 256];
        }
        const unsigned word = __ldg(arow + tile);
#pragma unroll
        for (int jj = 0; jj < 8; ++jj) {
            const int   j  = q * 8 + jj;
            const float s  = f1i + f2_s[tile * JT + j];
            const float e2 = __expf(s + s);
            const float t  = 1.0f - __fdividef(2.0f, e2 + 1.0f);   // tanh(s)
            float w = __expf(t);
            w = ((word >> j) & 1u) ? w : 0.0f;
            w_s[j * 64 + r] = w;
        }
        __syncthreads();

        // ---- phase B: dense accumulation ----
        const float* hq = h_s + q * 16;
#pragma unroll 8
        for (int j = 0; j < JT; ++j) {
            const float w = w_s[j * 64 + r];
            denom += w;
            unsigned long long w2;
            asm("mov.b64 %0, {%1, %1};" : "=l"(w2) : "f"(w));
            const ulonglong2* hp = (const ulonglong2*)(hq + j * FOUT);
#pragma unroll
            for (int kk = 0; kk < 4; ++kk) {
                const ulonglong2 p = hp[kk];
                acc[2 * kk]     = fma2(w2, p.x, acc[2 * kk]);
                acc[2 * kk + 1] = fma2(w2, p.y, acc[2 * kk + 1]);
            }
        }
        __syncthreads();
    }

    // ---- epilogue: divide, ELU, store (features disjoint per thread) ----
    const float inv = 1.0f / denom;
    float* op = out + (size_t)(b * NN + i) * FOUT + q * 16;
#pragma unroll
    for (int kk = 0; kk < 8; ++kk) {
        float lo, hi;
        asm("mov.b64 {%0, %1}, %2;" : "=f"(lo), "=f"(hi) : "l"(acc[kk]));
        lo *= inv; hi *= inv;
        lo = lo > 0.f ? lo : expm1f(lo);
        hi = hi > 0.f ? hi : expm1f(hi);
        *(float2*)(op + 2 * kk) = make_float2(lo, hi);
    }
}

// ---------------------------------------------------------------------------
extern "C" void kernel_launch(void* const* d_in, const int* in_sizes, int n_in,
                              void* d_out, int out_size) {
    const float* x   = (const float*)d_in[0];
    const int*   adj = (const int*)d_in[1];
    const float* W   = (const float*)d_in[2];
    const float* a   = (const float*)d_in[3];
    float*       out = (float*)d_out;

    k_proj<<<BB * NN / 64, 256>>>(x, W, a);
    k_pack<<<(BB * NN * NN) / (128 * 8), 256>>>(adj);
    k_attn<<<dim3(NN / 64, BB), 256>>>(out);
}

// round 4
// speedup vs baseline: 1.7539x; 1.7539x over previous
#include <cuda_runtime.h>
#include <cuda_fp16.h>
#include <cstdint>

#define BB 8
#define NN 2048
#define FIN 128
#define FOUT 64

// ---- scratch (static device arrays are allowed) ----
__device__ float  g_f1[BB * NN];
__device__ float  g_f2[BB * NN];
__device__ __half g_ht[BB * FOUT * NN];   // h transposed: [b][f][j], fp16

__device__ __forceinline__ float ex2f(float x) {
    float y; asm("ex2.approx.f32 %0, %1;" : "=f"(y) : "f"(x)); return y;
}
__device__ __forceinline__ float rcpf(float x) {
    float y; asm("rcp.approx.f32 %0, %1;" : "=f"(y) : "f"(x)); return y;
}
// w = exp(tanh(s)).  tanh = 1 - 2/(e^{2s}+1) via ex2+rcp, exp via ex2.
__device__ __forceinline__ float gat_w(float s) {
    const float e2 = ex2f(s * 2.8853900817779268f);   // 2*log2(e)
    const float r  = rcpf(e2 + 1.0f);
    const float t  = fmaf(-2.0f, r, 1.0f);
    return ex2f(t * 1.4426950408889634f);
}
__device__ __forceinline__ float eluf(float x) { return x > 0.f ? x : expm1f(x); }
__device__ __forceinline__ uint32_t packh2(float lo, float hi) {
    __half2 h = __floats2half2_rn(lo, hi);
    return *(uint32_t*)&h;
}

// ---------------------------------------------------------------------------
// Kernel A: h = x@W (f32), f1/f2 = h@a halves, emit h^T fp16 [b][f][j].
// 256 thr, 64 rows/CTA, 256 CTAs. Warp handles 8 rows; lane owns feature
// pair (2*lane, 2*lane+1). x read via warp-uniform LDG.128 (broadcast),
// W staged in smem. FMA-bound (~8-10us).
// ---------------------------------------------------------------------------
#define HP 72   // hsT pitch in halves (16B-aligned rows, conflict-friendly)

__global__ __launch_bounds__(256) void k_proj(const float* __restrict__ x,
                                              const float* __restrict__ W,
                                              const float* __restrict__ a) {
    __shared__ float  Ws[FIN * FOUT];       // 32 KB
    __shared__ __half hsT[FOUT * HP];       // 9 KB transpose buffer

    const int tid  = threadIdx.x;
    const int lane = tid & 31;
    const int warp = tid >> 5;
    const int b    = blockIdx.x >> 5;              // 32 blocks per batch
    const int jb   = (blockIdx.x & 31) * 64;       // row block within batch

    {
        const float4* Wsrc = (const float4*)W;
        float4*       Wdst = (float4*)Ws;
#pragma unroll
        for (int c = 0; c < 8; ++c) Wdst[tid + 256 * c] = Wsrc[tid + 256 * c];
    }
    const float2 av1 = *(const float2*)(a + 2 * lane);
    const float2 av2 = *(const float2*)(a + FOUT + 2 * lane);
    __syncthreads();

    const float* xr = x + ((size_t)b * NN + jb + warp * 8) * FIN;
    float2 acc[8];
#pragma unroll
    for (int r = 0; r < 8; ++r) acc[r] = make_float2(0.f, 0.f);

#pragma unroll 2
    for (int k4 = 0; k4 < FIN / 4; ++k4) {
        float4 xv[8];
#pragma unroll
        for (int r = 0; r < 8; ++r)
            xv[r] = __ldg((const float4*)(xr + (size_t)r * FIN) + k4);
#pragma unroll
        for (int kk = 0; kk < 4; ++kk) {
            const float2 wv = *(const float2*)&Ws[(k4 * 4 + kk) * FOUT + 2 * lane];
#pragma unroll
            for (int r = 0; r < 8; ++r) {
                const float xk = (kk == 0) ? xv[r].x : (kk == 1) ? xv[r].y
                               : (kk == 2) ? xv[r].z : xv[r].w;
                acc[r].x = fmaf(xk, wv.x, acc[r].x);
                acc[r].y = fmaf(xk, wv.y, acc[r].y);
            }
        }
    }

#pragma unroll
    for (int r = 0; r < 8; ++r) {
        const int rowloc = warp * 8 + r;
        hsT[(2 * lane) * HP + rowloc]     = __float2half_rn(acc[r].x);
        hsT[(2 * lane + 1) * HP + rowloc] = __float2half_rn(acc[r].y);
        float p1 = acc[r].x * av1.x + acc[r].y * av1.y;
        float p2 = acc[r].x * av2.x + acc[r].y * av2.y;
#pragma unroll
        for (int d = 16; d; d >>= 1) {
            p1 += __shfl_xor_sync(0xffffffffu, p1, d);
            p2 += __shfl_xor_sync(0xffffffffu, p2, d);
        }
        if (lane == 0) {
            g_f1[b * NN + jb + rowloc] = p1;
            g_f2[b * NN + jb + rowloc] = p2;
        }
    }
    __syncthreads();

    // coalesced write-out: 64 feats x 8 segs of 8 halves = 512 slots
#pragma unroll
    for (int i = 0; i < 2; ++i) {
        const int idx  = tid + i * 256;
        const int feat = idx >> 3;
        const int seg  = idx & 7;
        const uint4 v = *(const uint4*)&hsT[feat * HP + seg * 8];
        *(uint4*)(g_ht + ((size_t)(b * FOUT + feat)) * NN + jb + seg * 8) = v;
    }
}

// ---------------------------------------------------------------------------
// Kernel B: fused GAT attention on mma.sync.m16n8k16 (f16 in, f32 acc).
// 256 thr = 8 warps; warp owns 16 i-rows x 64 features; 128 CTAs.
// Scores computed straight into the A-fragment registers; B fragments from
// an h^T smem tile (pitch 72 halves -> conflict-free LDS.32).
// Denominators accumulated in registers, quad-shuffle reduced.
// ---------------------------------------------------------------------------
#define PITCH 72
#define NSTAGE 32            // 64 j per stage
#define NKS 128              // 16-j mma steps total

__global__ __launch_bounds__(256) void k_attn(const int* __restrict__ adj,
                                              float* __restrict__ out) {
    __shared__ float  f2s[NN];              // 8 KB
    __shared__ __half hTs[FOUT * PITCH];    // 9 KB

    const int tid  = threadIdx.x;
    const int warp = tid >> 5;
    const int lane = tid & 31;
    const int t    = lane & 3;
    const int g    = lane >> 2;
    const int b    = blockIdx.x >> 4;             // 16 blocks per batch
    const int i0   = (blockIdx.x & 15) * 128;
    const int r0   = i0 + warp * 16 + g;
    const int r1   = r0 + 8;

    const float f1_0 = g_f1[b * NN + r0];
    const float f1_1 = g_f1[b * NN + r1];
    for (int l = tid; l < NN; l += 256) f2s[l] = g_f2[b * NN + l];

    const int* arow0 = adj + ((size_t)b * NN + r0) * NN;
    const int* arow1 = adj + ((size_t)b * NN + r1) * NN;
    const __half* hb = g_ht + (size_t)b * FOUT * NN;

    // stage-load slots: 64 feats x 8 segs (8 halves each) = 512 -> 2/thread
    const int f_a = tid >> 3, f_b = (tid + 256) >> 3;
    const int sg  = tid & 7;
    uint4 stA = *(const uint4*)(hb + (size_t)f_a * NN + sg * 8);
    uint4 stB = *(const uint4*)(hb + (size_t)f_b * NN + sg * 8);

    // adjacency prefetch (kstep 0)
    int2 pa0 = *(const int2*)(arow0 + 2 * t);
    int2 pa1 = *(const int2*)(arow0 + 8 + 2 * t);
    int2 pa2 = *(const int2*)(arow1 + 2 * t);
    int2 pa3 = *(const int2*)(arow1 + 8 + 2 * t);

    float acc[32];
#pragma unroll
    for (int k = 0; k < 32; ++k) acc[k] = 0.f;
    float ds0 = 0.f, ds1 = 0.f;

    for (int s = 0; s < NSTAGE; ++s) {
        __syncthreads();
        *(uint4*)(hTs + f_a * PITCH + sg * 8) = stA;
        *(uint4*)(hTs + f_b * PITCH + sg * 8) = stB;
        if (s + 1 < NSTAGE) {
            stA = *(const uint4*)(hb + (size_t)f_a * NN + (s + 1) * 64 + sg * 8);
            stB = *(const uint4*)(hb + (size_t)f_b * NN + (s + 1) * 64 + sg * 8);
        }
        __syncthreads();

#pragma unroll
        for (int kk = 0; kk < 4; ++kk) {
            const int ks = s * 4 + kk;
            const int j0 = ks * 16;
            // prefetch next kstep's adjacency
            const int jn = (ks + 1 < NKS) ? (ks + 1) * 16 : 0;
            const int2 na0 = *(const int2*)(arow0 + jn + 2 * t);
            const int2 na1 = *(const int2*)(arow0 + jn + 8 + 2 * t);
            const int2 na2 = *(const int2*)(arow1 + jn + 2 * t);
            const int2 na3 = *(const int2*)(arow1 + jn + 8 + 2 * t);

            const float2 flo = *(const float2*)&f2s[j0 + 2 * t];
            const float2 fhi = *(const float2*)&f2s[j0 + 8 + 2 * t];

            float w00 = gat_w(f1_0 + flo.x), w01 = gat_w(f1_0 + flo.y);
            float w02 = gat_w(f1_0 + fhi.x), w03 = gat_w(f1_0 + fhi.y);
            float w10 = gat_w(f1_1 + flo.x), w11 = gat_w(f1_1 + flo.y);
            float w12 = gat_w(f1_1 + fhi.x), w13 = gat_w(f1_1 + fhi.y);
            w00 = pa0.x > 0 ? w00 : 0.f;  w01 = pa0.y > 0 ? w01 : 0.f;
            w02 = pa1.x > 0 ? w02 : 0.f;  w03 = pa1.y > 0 ? w03 : 0.f;
            w10 = pa2.x > 0 ? w10 : 0.f;  w11 = pa2.y > 0 ? w11 : 0.f;
            w12 = pa3.x > 0 ? w12 : 0.f;  w13 = pa3.y > 0 ? w13 : 0.f;
            ds0 += (w00 + w01) + (w02 + w03);
            ds1 += (w10 + w11) + (w12 + w13);

            // A fragment (m16k16 row-major): rows {g, g+8}, cols {2t,2t+1,2t+8,2t+9}
            const uint32_t A0 = packh2(w00, w01);   // [g][2t..]
            const uint32_t A1 = packh2(w10, w11);   // [g+8][2t..]
            const uint32_t A2 = packh2(w02, w03);   // [g][2t+8..]
            const uint32_t A3 = packh2(w12, w13);   // [g+8][2t+8..]

            const int ko = kk * 16 + 2 * t;
#pragma unroll
            for (int nb = 0; nb < 8; ++nb) {
                const __half* bp = hTs + (nb * 8 + g) * PITCH + ko;
                const uint32_t B0 = *(const uint32_t*)bp;        // B[2t..][n]
                const uint32_t B1 = *(const uint32_t*)(bp + 8);  // B[2t+8..][n]
                float* c = acc + nb * 4;
                asm volatile(
                    "mma.sync.aligned.m16n8k16.row.col.f32.f16.f16.f32 "
                    "{%0,%1,%2,%3}, {%4,%5,%6,%7}, {%8,%9}, {%0,%1,%2,%3};"
                    : "+f"(c[0]), "+f"(c[1]), "+f"(c[2]), "+f"(c[3])
                    : "r"(A0), "r"(A1), "r"(A2), "r"(A3), "r"(B0), "r"(B1));
            }
            pa0 = na0; pa1 = na1; pa2 = na2; pa3 = na3;
        }
    }

    // denominator: reduce over the 4 quad lanes (cols are split across t)
    ds0 += __shfl_xor_sync(0xffffffffu, ds0, 1);
    ds0 += __shfl_xor_sync(0xffffffffu, ds0, 2);
    ds1 += __shfl_xor_sync(0xffffffffu, ds1, 1);
    ds1 += __shfl_xor_sync(0xffffffffu, ds1, 2);
    const float inv0 = 1.0f / ds0;
    const float inv1 = 1.0f / ds1;

    float* o0 = out + ((size_t)b * NN + r0) * FOUT;
    float* o1 = out + ((size_t)b * NN + r1) * FOUT;
#pragma unroll
    for (int nb = 0; nb < 8; ++nb) {
        float2 v0, v1;
        v0.x = eluf(acc[nb * 4 + 0] * inv0);
        v0.y = eluf(acc[nb * 4 + 1] * inv0);
        v1.x = eluf(acc[nb * 4 + 2] * inv1);
        v1.y = eluf(acc[nb * 4 + 3] * inv1);
        *(float2*)(o0 + nb * 8 + 2 * t) = v0;
        *(float2*)(o1 + nb * 8 + 2 * t) = v1;
    }
}

// ---------------------------------------------------------------------------
extern "C" void kernel_launch(void* const* d_in, const int* in_sizes, int n_in,
                              void* d_out, int out_size) {
    const float* x   = (const float*)d_in[0];
    const int*   adj = (const int*)d_in[1];
    const float* W   = (const float*)d_in[2];
    const float* a   = (const float*)d_in[3];
    float*       out = (float*)d_out;

    k_proj<<<BB * NN / 64, 256>>>(x, W, a);
    k_attn<<<dim3(BB * NN / 128), 256>>>(adj, out);
}

// round 5
// speedup vs baseline: 2.5855x; 1.4741x over previous
#include <cuda_runtime.h>
#include <cuda_fp16.h>
#include <cstdint>

#define BB 8
#define NN 2048
#define FIN 128
#define FOUT 64
#define JSPLIT 4
#define JLEN (NN / JSPLIT)   // 512

// ---- scratch (static device arrays are allowed) ----
__device__ float  g_f1[BB * NN];
__device__ float  g_f2[BB * NN];
__device__ __half g_ht[BB * FOUT * NN];              // h^T fp16 [b][f][j]
__device__ float  g_pout[JSPLIT * BB * NN * FOUT];   // 16 MB partial PV sums
__device__ float  g_pden[JSPLIT * BB * NN];          // partial denominators

__device__ __forceinline__ float ex2f(float x) {
    float y; asm("ex2.approx.f32 %0, %1;" : "=f"(y) : "f"(x)); return y;
}
__device__ __forceinline__ float rcpf(float x) {
    float y; asm("rcp.approx.f32 %0, %1;" : "=f"(y) : "f"(x)); return y;
}
// w = exp(tanh(s)).  tanh = 1 - 2/(e^{2s}+1) via ex2+rcp, exp via ex2.
__device__ __forceinline__ float gat_w(float s) {
    const float e2 = ex2f(s * 2.8853900817779268f);   // 2*log2(e)
    const float r  = rcpf(e2 + 1.0f);
    const float t  = fmaf(-2.0f, r, 1.0f);
    return ex2f(t * 1.4426950408889634f);
}
__device__ __forceinline__ float eluf(float x) { return x > 0.f ? x : expm1f(x); }
__device__ __forceinline__ uint32_t packh2(float lo, float hi) {
    __half2 h = __floats2half2_rn(lo, hi);
    return *(uint32_t*)&h;
}

// ---------------------------------------------------------------------------
// Kernel A: h = x@W (f32), f1/f2 = h@a halves, emit h^T fp16 [b][f][j].
// ---------------------------------------------------------------------------
#define HP 72

__global__ __launch_bounds__(256) void k_proj(const float* __restrict__ x,
                                              const float* __restrict__ W,
                                              const float* __restrict__ a) {
    __shared__ float  Ws[FIN * FOUT];       // 32 KB
    __shared__ __half hsT[FOUT * HP];       // 9 KB

    const int tid  = threadIdx.x;
    const int lane = tid & 31;
    const int warp = tid >> 5;
    const int b    = blockIdx.x >> 5;
    const int jb   = (blockIdx.x & 31) * 64;

    {
        const float4* Wsrc = (const float4*)W;
        float4*       Wdst = (float4*)Ws;
#pragma unroll
        for (int c = 0; c < 8; ++c) Wdst[tid + 256 * c] = Wsrc[tid + 256 * c];
    }
    const float2 av1 = *(const float2*)(a + 2 * lane);
    const float2 av2 = *(const float2*)(a + FOUT + 2 * lane);
    __syncthreads();

    const float* xr = x + ((size_t)b * NN + jb + warp * 8) * FIN;
    float2 acc[8];
#pragma unroll
    for (int r = 0; r < 8; ++r) acc[r] = make_float2(0.f, 0.f);

#pragma unroll 2
    for (int k4 = 0; k4 < FIN / 4; ++k4) {
        float4 xv[8];
#pragma unroll
        for (int r = 0; r < 8; ++r)
            xv[r] = __ldg((const float4*)(xr + (size_t)r * FIN) + k4);
#pragma unroll
        for (int kk = 0; kk < 4; ++kk) {
            const float2 wv = *(const float2*)&Ws[(k4 * 4 + kk) * FOUT + 2 * lane];
#pragma unroll
            for (int r = 0; r < 8; ++r) {
                const float xk = (kk == 0) ? xv[r].x : (kk == 1) ? xv[r].y
                               : (kk == 2) ? xv[r].z : xv[r].w;
                acc[r].x = fmaf(xk, wv.x, acc[r].x);
                acc[r].y = fmaf(xk, wv.y, acc[r].y);
            }
        }
    }

#pragma unroll
    for (int r = 0; r < 8; ++r) {
        const int rowloc = warp * 8 + r;
        hsT[(2 * lane) * HP + rowloc]     = __float2half_rn(acc[r].x);
        hsT[(2 * lane + 1) * HP + rowloc] = __float2half_rn(acc[r].y);
        float p1 = acc[r].x * av1.x + acc[r].y * av1.y;
        float p2 = acc[r].x * av2.x + acc[r].y * av2.y;
#pragma unroll
        for (int d = 16; d; d >>= 1) {
            p1 += __shfl_xor_sync(0xffffffffu, p1, d);
            p2 += __shfl_xor_sync(0xffffffffu, p2, d);
        }
        if (lane == 0) {
            g_f1[b * NN + jb + rowloc] = p1;
            g_f2[b * NN + jb + rowloc] = p2;
        }
    }
    __syncthreads();

#pragma unroll
    for (int i = 0; i < 2; ++i) {
        const int idx  = tid + i * 256;
        const int feat = idx >> 3;
        const int seg  = idx & 7;
        const uint4 v = *(const uint4*)&hsT[feat * HP + seg * 8];
        *(uint4*)(g_ht + ((size_t)(b * FOUT + feat)) * NN + jb + seg * 8) = v;
    }
}

// ---------------------------------------------------------------------------
// Kernel B: fused GAT attention on mma.sync.m16n8k16, j-split x4.
// Grid (16*JSPLIT, BB); 256 thr = 8 warps; warp owns 16 i-rows x 64 f over a
// 512-j slice. Emits raw partial sums + partial denominators.
// ---------------------------------------------------------------------------
#define PITCH 72
#define NSTAGE (JLEN / 64)   // 8
#define NKS (JLEN / 16)      // 32

__global__ __launch_bounds__(256, 3) void k_attn(const int* __restrict__ adj) {
    __shared__ float  f2s[JLEN];            // 2 KB
    __shared__ __half hTs[FOUT * PITCH];    // 9 KB

    const int tid   = threadIdx.x;
    const int warp  = tid >> 5;
    const int lane  = tid & 31;
    const int t     = lane & 3;
    const int g     = lane >> 2;
    const int b     = blockIdx.y;
    const int split = blockIdx.x & 3;
    const int i0    = (blockIdx.x >> 2) * 128;
    const int jb    = split * JLEN;
    const int r0    = i0 + warp * 16 + g;
    const int r1    = r0 + 8;

    const float f1_0 = g_f1[b * NN + r0];
    const float f1_1 = g_f1[b * NN + r1];
    for (int l = tid; l < JLEN; l += 256) f2s[l] = g_f2[b * NN + jb + l];

    const int* arow0 = adj + ((size_t)b * NN + r0) * NN + jb;
    const int* arow1 = adj + ((size_t)b * NN + r1) * NN + jb;
    const __half* hb = g_ht + (size_t)b * FOUT * NN + jb;

    const int f_a = tid >> 3, f_b = (tid + 256) >> 3;
    const int sg  = tid & 7;
    uint4 stA = *(const uint4*)(hb + (size_t)f_a * NN + sg * 8);
    uint4 stB = *(const uint4*)(hb + (size_t)f_b * NN + sg * 8);

    int2 pa0 = *(const int2*)(arow0 + 2 * t);
    int2 pa1 = *(const int2*)(arow0 + 8 + 2 * t);
    int2 pa2 = *(const int2*)(arow1 + 2 * t);
    int2 pa3 = *(const int2*)(arow1 + 8 + 2 * t);

    float acc[32];
#pragma unroll
    for (int k = 0; k < 32; ++k) acc[k] = 0.f;
    float ds0 = 0.f, ds1 = 0.f;

    for (int s = 0; s < NSTAGE; ++s) {
        __syncthreads();
        *(uint4*)(hTs + f_a * PITCH + sg * 8) = stA;
        *(uint4*)(hTs + f_b * PITCH + sg * 8) = stB;
        if (s + 1 < NSTAGE) {
            stA = *(const uint4*)(hb + (size_t)f_a * NN + (s + 1) * 64 + sg * 8);
            stB = *(const uint4*)(hb + (size_t)f_b * NN + (s + 1) * 64 + sg * 8);
        }
        __syncthreads();

#pragma unroll
        for (int kk = 0; kk < 4; ++kk) {
            const int ks = s * 4 + kk;
            const int j0 = ks * 16;
            const int jn = (ks + 1 < NKS) ? (ks + 1) * 16 : 0;
            const int2 na0 = *(const int2*)(arow0 + jn + 2 * t);
            const int2 na1 = *(const int2*)(arow0 + jn + 8 + 2 * t);
            const int2 na2 = *(const int2*)(arow1 + jn + 2 * t);
            const int2 na3 = *(const int2*)(arow1 + jn + 8 + 2 * t);

            const float2 flo = *(const float2*)&f2s[j0 + 2 * t];
            const float2 fhi = *(const float2*)&f2s[j0 + 8 + 2 * t];

            float w00 = gat_w(f1_0 + flo.x), w01 = gat_w(f1_0 + flo.y);
            float w02 = gat_w(f1_0 + fhi.x), w03 = gat_w(f1_0 + fhi.y);
            float w10 = gat_w(f1_1 + flo.x), w11 = gat_w(f1_1 + flo.y);
            float w12 = gat_w(f1_1 + fhi.x), w13 = gat_w(f1_1 + fhi.y);
            w00 = pa0.x > 0 ? w00 : 0.f;  w01 = pa0.y > 0 ? w01 : 0.f;
            w02 = pa1.x > 0 ? w02 : 0.f;  w03 = pa1.y > 0 ? w03 : 0.f;
            w10 = pa2.x > 0 ? w10 : 0.f;  w11 = pa2.y > 0 ? w11 : 0.f;
            w12 = pa3.x > 0 ? w12 : 0.f;  w13 = pa3.y > 0 ? w13 : 0.f;
            ds0 += (w00 + w01) + (w02 + w03);
            ds1 += (w10 + w11) + (w12 + w13);

            const uint32_t A0 = packh2(w00, w01);
            const uint32_t A1 = packh2(w10, w11);
            const uint32_t A2 = packh2(w02, w03);
            const uint32_t A3 = packh2(w12, w13);

            const int ko = kk * 16 + 2 * t;
#pragma unroll
            for (int nb = 0; nb < 8; ++nb) {
                const __half* bp = hTs + (nb * 8 + g) * PITCH + ko;
                const uint32_t B0 = *(const uint32_t*)bp;
                const uint32_t B1 = *(const uint32_t*)(bp + 8);
                float* c = acc + nb * 4;
                asm volatile(
                    "mma.sync.aligned.m16n8k16.row.col.f32.f16.f16.f32 "
                    "{%0,%1,%2,%3}, {%4,%5,%6,%7}, {%8,%9}, {%0,%1,%2,%3};"
                    : "+f"(c[0]), "+f"(c[1]), "+f"(c[2]), "+f"(c[3])
                    : "r"(A0), "r"(A1), "r"(A2), "r"(A3), "r"(B0), "r"(B1));
            }
            pa0 = na0; pa1 = na1; pa2 = na2; pa3 = na3;
        }
    }

    ds0 += __shfl_xor_sync(0xffffffffu, ds0, 1);
    ds0 += __shfl_xor_sync(0xffffffffu, ds0, 2);
    ds1 += __shfl_xor_sync(0xffffffffu, ds1, 1);
    ds1 += __shfl_xor_sync(0xffffffffu, ds1, 2);

    const size_t pbase = (size_t)(split * BB + b);
    if (t == 0) {
        g_pden[pbase * NN + r0] = ds0;
        g_pden[pbase * NN + r1] = ds1;
    }
    float* o0 = g_pout + (pbase * NN + r0) * FOUT;
    float* o1 = g_pout + (pbase * NN + r1) * FOUT;
#pragma unroll
    for (int nb = 0; nb < 8; ++nb) {
        *(float2*)(o0 + nb * 8 + 2 * t) = make_float2(acc[nb * 4 + 0], acc[nb * 4 + 1]);
        *(float2*)(o1 + nb * 8 + 2 * t) = make_float2(acc[nb * 4 + 2], acc[nb * 4 + 3]);
    }
}

// ---------------------------------------------------------------------------
// Kernel C: combine partials -> divide -> ELU -> out. Memory-bound (~3us).
// One float4 per thread; 16 threads per row.
// ---------------------------------------------------------------------------
__global__ __launch_bounds__(256) void k_comb(float* __restrict__ out) {
    const int idx = blockIdx.x * 256 + threadIdx.x;   // 0 .. BB*NN*16-1
    const int row = idx >> 4;                         // global row (b*NN+i)
    const int seg = idx & 15;

    float den = 0.f;
#pragma unroll
    for (int s = 0; s < JSPLIT; ++s) den += g_pden[(size_t)s * BB * NN + row];
    const float inv = 1.0f / den;

    float4 v = make_float4(0.f, 0.f, 0.f, 0.f);
#pragma unroll
    for (int s = 0; s < JSPLIT; ++s) {
        const float4 p = *(const float4*)(g_pout +
            ((size_t)s * BB * NN + row) * FOUT + seg * 4);
        v.x += p.x; v.y += p.y; v.z += p.z; v.w += p.w;
    }
    v.x = eluf(v.x * inv); v.y = eluf(v.y * inv);
    v.z = eluf(v.z * inv); v.w = eluf(v.w * inv);
    *(float4*)(out + (size_t)row * FOUT + seg * 4) = v;
}

// ---------------------------------------------------------------------------
extern "C" void kernel_launch(void* const* d_in, const int* in_sizes, int n_in,
                              void* d_out, int out_size) {
    const float* x   = (const float*)d_in[0];
    const int*   adj = (const int*)d_in[1];
    const float* W   = (const float*)d_in[2];
    const float* a   = (const float*)d_in[3];
    float*       out = (float*)d_out;

    k_proj<<<BB * NN / 64, 256>>>(x, W, a);
    k_attn<<<dim3(16 * JSPLIT, BB), 256>>>(adj);
    k_comb<<<BB * NN * 16 / 256, 256>>>(out);
}

// round 6
// speedup vs baseline: 3.4208x; 1.3231x over previous
#include <cuda_runtime.h>
#include <cuda_fp16.h>
#include <cstdint>

#define BB 8
#define NN 2048
#define FIN 128
#define FOUT 64
#define JSPLIT 8
#define JLEN (NN / JSPLIT)   // 256

// ---- scratch (static device arrays are allowed) ----
__device__ float  g_f1[BB * NN];
__device__ float  g_f2[BB * NN];
__device__ __half g_ht[BB * FOUT * NN];              // h^T fp16 [b][f][j]
__device__ float  g_pout[JSPLIT * BB * NN * FOUT];   // 32 MB partial PV sums
__device__ float  g_pden[JSPLIT * BB * NN];          // partial denominators

__device__ __forceinline__ float ex2f(float x) {
    float y; asm("ex2.approx.f32 %0, %1;" : "=f"(y) : "f"(x)); return y;
}
__device__ __forceinline__ float rcpf(float x) {
    float y; asm("rcp.approx.f32 %0, %1;" : "=f"(y) : "f"(x)); return y;
}
// w = exp(tanh(s)).  tanh = 1 - 2/(e^{2s}+1) via ex2+rcp, exp via ex2.
__device__ __forceinline__ float gat_w(float s) {
    const float e2 = ex2f(s * 2.8853900817779268f);   // 2*log2(e)
    const float r  = rcpf(e2 + 1.0f);
    const float t  = fmaf(-2.0f, r, 1.0f);
    return ex2f(t * 1.4426950408889634f);
}
__device__ __forceinline__ float eluf(float x) { return x > 0.f ? x : expm1f(x); }
__device__ __forceinline__ uint32_t packh2(float lo, float hi) {
    __half2 h = __floats2half2_rn(lo, hi);
    return *(uint32_t*)&h;
}
__device__ __forceinline__ uint32_t smem_u32(const void* p) {
    uint32_t a;
    asm("{ .reg .u64 t; cvta.to.shared.u64 t, %1; cvt.u32.u64 %0, t; }"
        : "=r"(a) : "l"(p));
    return a;
}
__device__ __forceinline__ void cp16(uint32_t dst, const void* src) {
    asm volatile("cp.async.cg.shared.global [%0], [%1], 16;"
                 :: "r"(dst), "l"(src) : "memory");
}

// ---------------------------------------------------------------------------
// Kernel A: h = x@W (f32), f1/f2 = h@a halves, emit h^T fp16 [b][f][j].
// 512 CTAs x 256 thr, 32 rows/CTA (warp owns 4 rows, lane owns feature pair).
// ---------------------------------------------------------------------------
#define HP 40   // hsT pitch in halves (80B rows, 16B aligned)

__global__ __launch_bounds__(256) void k_proj(const float* __restrict__ x,
                                              const float* __restrict__ W,
                                              const float* __restrict__ a) {
    __shared__ float  Ws[FIN * FOUT];       // 32 KB
    __shared__ __half hsT[FOUT * HP];       // 5 KB

    const int tid  = threadIdx.x;
    const int lane = tid & 31;
    const int warp = tid >> 5;
    const int b    = blockIdx.x >> 6;              // 64 blocks per batch
    const int jb   = (blockIdx.x & 63) * 32;       // 32-row block

    {
        const float4* Wsrc = (const float4*)W;
        float4*       Wdst = (float4*)Ws;
#pragma unroll
        for (int c = 0; c < 8; ++c) Wdst[tid + 256 * c] = Wsrc[tid + 256 * c];
    }
    const float2 av1 = *(const float2*)(a + 2 * lane);
    const float2 av2 = *(const float2*)(a + FOUT + 2 * lane);
    __syncthreads();

    const float* xr = x + ((size_t)b * NN + jb + warp * 4) * FIN;
    float2 acc[4];
#pragma unroll
    for (int r = 0; r < 4; ++r) acc[r] = make_float2(0.f, 0.f);

#pragma unroll 4
    for (int k4 = 0; k4 < FIN / 4; ++k4) {
        float4 xv[4];
#pragma unroll
        for (int r = 0; r < 4; ++r)
            xv[r] = __ldg((const float4*)(xr + (size_t)r * FIN) + k4);
#pragma unroll
        for (int kk = 0; kk < 4; ++kk) {
            const float2 wv = *(const float2*)&Ws[(k4 * 4 + kk) * FOUT + 2 * lane];
#pragma unroll
            for (int r = 0; r < 4; ++r) {
                const float xk = (kk == 0) ? xv[r].x : (kk == 1) ? xv[r].y
                               : (kk == 2) ? xv[r].z : xv[r].w;
                acc[r].x = fmaf(xk, wv.x, acc[r].x);
                acc[r].y = fmaf(xk, wv.y, acc[r].y);
            }
        }
    }

#pragma unroll
    for (int r = 0; r < 4; ++r) {
        const int rowloc = warp * 4 + r;
        hsT[(2 * lane) * HP + rowloc]     = __float2half_rn(acc[r].x);
        hsT[(2 * lane + 1) * HP + rowloc] = __float2half_rn(acc[r].y);
        float p1 = acc[r].x * av1.x + acc[r].y * av1.y;
        float p2 = acc[r].x * av2.x + acc[r].y * av2.y;
#pragma unroll
        for (int d = 16; d; d >>= 1) {
            p1 += __shfl_xor_sync(0xffffffffu, p1, d);
            p2 += __shfl_xor_sync(0xffffffffu, p2, d);
        }
        if (lane == 0) {
            g_f1[b * NN + jb + rowloc] = p1;
            g_f2[b * NN + jb + rowloc] = p2;
        }
    }
    __syncthreads();

    // 64 feats x 4 segs of 8 halves = 256 slots, one per thread
    {
        const int feat = tid >> 2;
        const int seg  = tid & 3;
        const uint4 v = *(const uint4*)&hsT[feat * HP + seg * 8];
        *(uint4*)(g_ht + ((size_t)(b * FOUT + feat)) * NN + jb + seg * 8) = v;
    }
}

// ---------------------------------------------------------------------------
// Kernel B: fused GAT attention on mma.sync.m16n8k16, j-split x8.
// Grid (16, 8, 8) = 1024 CTAs; 256 thr = 8 warps; warp owns 16 i x 64 f over
// a 256-j slice. h^T tiles double-buffered via cp.async. 4 CTAs/SM target.
// ---------------------------------------------------------------------------
#define PITCH 72
#define NSTAGE (JLEN / 64)   // 4
#define NKS (JLEN / 16)      // 16

__global__ __launch_bounds__(256, 4) void k_attn(const int* __restrict__ adj) {
    __shared__ float  f2s[JLEN];                 // 1 KB
    __shared__ __half hTs[2][FOUT * PITCH];      // 2 x 9 KB

    const int tid   = threadIdx.x;
    const int warp  = tid >> 5;
    const int lane  = tid & 31;
    const int t     = lane & 3;
    const int g     = lane >> 2;
    const int b     = blockIdx.z;
    const int split = blockIdx.y;
    const int i0    = blockIdx.x * 128;
    const int jb    = split * JLEN;
    const int r0    = i0 + warp * 16 + g;
    const int r1    = r0 + 8;

    const float f1_0 = g_f1[b * NN + r0];
    const float f1_1 = g_f1[b * NN + r1];
    f2s[tid] = g_f2[b * NN + jb + tid];

    const int* arow0 = adj + ((size_t)b * NN + r0) * NN + jb;
    const int* arow1 = adj + ((size_t)b * NN + r1) * NN + jb;
    const __half* hb = g_ht + (size_t)b * FOUT * NN + jb;

    // cp.async slots: 64 feats x 8 segs of 8 halves = 512 -> 2 per thread
    const int f_a = tid >> 3, f_b = (tid + 256) >> 3;
    const int sg  = tid & 7;
    const uint32_t dA = smem_u32(&hTs[0][f_a * PITCH + sg * 8]) & 0xFFFFFFFFu;
    const uint32_t dB = smem_u32(&hTs[0][f_b * PITCH + sg * 8]) & 0xFFFFFFFFu;
    const uint32_t bufstep = (uint32_t)(FOUT * PITCH * 2);   // bytes between buffers
    const __half* sA = hb + (size_t)f_a * NN + sg * 8;
    const __half* sB = hb + (size_t)f_b * NN + sg * 8;

    // prologue: stage 0
    cp16(dA, sA);
    cp16(dB, sB);
    asm volatile("cp.async.commit_group;" ::: "memory");

    int2 pa0 = *(const int2*)(arow0 + 2 * t);
    int2 pa1 = *(const int2*)(arow0 + 8 + 2 * t);
    int2 pa2 = *(const int2*)(arow1 + 2 * t);
    int2 pa3 = *(const int2*)(arow1 + 8 + 2 * t);

    float acc[32];
#pragma unroll
    for (int k = 0; k < 32; ++k) acc[k] = 0.f;
    float ds0 = 0.f, ds1 = 0.f;

#pragma unroll
    for (int s = 0; s < NSTAGE; ++s) {
        if (s + 1 < NSTAGE) {
            const uint32_t db = ((s + 1) & 1) ? bufstep : 0u;
            cp16(dA + db, sA + (s + 1) * 64);
            cp16(dB + db, sB + (s + 1) * 64);
            asm volatile("cp.async.commit_group;" ::: "memory");
            asm volatile("cp.async.wait_group 1;" ::: "memory");
        } else {
            asm volatile("cp.async.wait_group 0;" ::: "memory");
        }
        __syncthreads();
        const __half* hcur = hTs[s & 1];

#pragma unroll
        for (int kk = 0; kk < 4; ++kk) {
            const int ks = s * 4 + kk;
            const int j0 = ks * 16;
            const int jn = (ks + 1 < NKS) ? (ks + 1) * 16 : 0;
            const int2 na0 = *(const int2*)(arow0 + jn + 2 * t);
            const int2 na1 = *(const int2*)(arow0 + jn + 8 + 2 * t);
            const int2 na2 = *(const int2*)(arow1 + jn + 2 * t);
            const int2 na3 = *(const int2*)(arow1 + jn + 8 + 2 * t);

            const float2 flo = *(const float2*)&f2s[j0 + 2 * t];
            const float2 fhi = *(const float2*)&f2s[j0 + 8 + 2 * t];

            float w00 = gat_w(f1_0 + flo.x), w01 = gat_w(f1_0 + flo.y);
            float w02 = gat_w(f1_0 + fhi.x), w03 = gat_w(f1_0 + fhi.y);
            float w10 = gat_w(f1_1 + flo.x), w11 = gat_w(f1_1 + flo.y);
            float w12 = gat_w(f1_1 + fhi.x), w13 = gat_w(f1_1 + fhi.y);
            w00 = pa0.x > 0 ? w00 : 0.f;  w01 = pa0.y > 0 ? w01 : 0.f;
            w02 = pa1.x > 0 ? w02 : 0.f;  w03 = pa1.y > 0 ? w03 : 0.f;
            w10 = pa2.x > 0 ? w10 : 0.f;  w11 = pa2.y > 0 ? w11 : 0.f;
            w12 = pa3.x > 0 ? w12 : 0.f;  w13 = pa3.y > 0 ? w13 : 0.f;
            ds0 += (w00 + w01) + (w02 + w03);
            ds1 += (w10 + w11) + (w12 + w13);

            const uint32_t A0 = packh2(w00, w01);
            const uint32_t A1 = packh2(w10, w11);
            const uint32_t A2 = packh2(w02, w03);
            const uint32_t A3 = packh2(w12, w13);

            const int ko = kk * 16 + 2 * t;
#pragma unroll
            for (int nb = 0; nb < 8; ++nb) {
                const __half* bp = hcur + (nb * 8 + g) * PITCH + ko;
                const uint32_t B0 = *(const uint32_t*)bp;
                const uint32_t B1 = *(const uint32_t*)(bp + 8);
                float* c = acc + nb * 4;
                asm volatile(
                    "mma.sync.aligned.m16n8k16.row.col.f32.f16.f16.f32 "
                    "{%0,%1,%2,%3}, {%4,%5,%6,%7}, {%8,%9}, {%0,%1,%2,%3};"
                    : "+f"(c[0]), "+f"(c[1]), "+f"(c[2]), "+f"(c[3])
                    : "r"(A0), "r"(A1), "r"(A2), "r"(A3), "r"(B0), "r"(B1));
            }
            pa0 = na0; pa1 = na1; pa2 = na2; pa3 = na3;
        }
        __syncthreads();
    }

    ds0 += __shfl_xor_sync(0xffffffffu, ds0, 1);
    ds0 += __shfl_xor_sync(0xffffffffu, ds0, 2);
    ds1 += __shfl_xor_sync(0xffffffffu, ds1, 1);
    ds1 += __shfl_xor_sync(0xffffffffu, ds1, 2);

    const size_t pbase = (size_t)(split * BB + b);
    if (t == 0) {
        g_pden[pbase * NN + r0] = ds0;
        g_pden[pbase * NN + r1] = ds1;
    }
    float* o0 = g_pout + (pbase * NN + r0) * FOUT;
    float* o1 = g_pout + (pbase * NN + r1) * FOUT;
#pragma unroll
    for (int nb = 0; nb < 8; ++nb) {
        *(float2*)(o0 + nb * 8 + 2 * t) = make_float2(acc[nb * 4 + 0], acc[nb * 4 + 1]);
        *(float2*)(o1 + nb * 8 + 2 * t) = make_float2(acc[nb * 4 + 2], acc[nb * 4 + 3]);
    }
}

// ---------------------------------------------------------------------------
// Kernel C: combine partials -> divide -> ELU -> out. Memory-bound (~6us).
// ---------------------------------------------------------------------------
__global__ __launch_bounds__(256) void k_comb(float* __restrict__ out) {
    const int idx = blockIdx.x * 256 + threadIdx.x;   // 0 .. BB*NN*16-1
    const int row = idx >> 4;
    const int seg = idx & 15;

    float den = 0.f;
#pragma unroll
    for (int s = 0; s < JSPLIT; ++s) den += g_pden[(size_t)s * BB * NN + row];
    const float inv = 1.0f / den;

    float4 v = make_float4(0.f, 0.f, 0.f, 0.f);
#pragma unroll
    for (int s = 0; s < JSPLIT; ++s) {
        const float4 p = *(const float4*)(g_pout +
            ((size_t)s * BB * NN + row) * FOUT + seg * 4);
        v.x += p.x; v.y += p.y; v.z += p.z; v.w += p.w;
    }
    v.x = eluf(v.x * inv); v.y = eluf(v.y * inv);
    v.z = eluf(v.z * inv); v.w = eluf(v.w * inv);
    *(float4*)(out + (size_t)row * FOUT + seg * 4) = v;
}

// ---------------------------------------------------------------------------
extern "C" void kernel_launch(void* const* d_in, const int* in_sizes, int n_in,
                              void* d_out, int out_size) {
    const float* x   = (const float*)d_in[0];
    const int*   adj = (const int*)d_in[1];
    const float* W   = (const float*)d_in[2];
    const float* a   = (const float*)d_in[3];
    float*       out = (float*)d_out;

    k_proj<<<BB * NN / 32, 256>>>(x, W, a);
    k_attn<<<dim3(16, JSPLIT, BB), 256>>>(adj);
    k_comb<<<BB * NN * 16 / 256, 256>>>(out);
}

// round 7
// speedup vs baseline: 3.4969x; 1.0222x over previous
#include <cuda_runtime.h>
#include <cuda_fp16.h>
#include <cstdint>

#define BB 8
#define NN 2048
#define FIN 128
#define FOUT 64
#define JSPLIT 8
#define JLEN (NN / JSPLIT)   // 256

// ---- scratch (static device arrays are allowed) ----
__device__ float  g_f1[BB * NN];
__device__ float  g_f2[BB * NN];
__device__ __half g_ht[BB * FOUT * NN];              // h^T fp16 [b][f][j]
__device__ float  g_pout[JSPLIT * BB * NN * FOUT];   // 32 MB partial PV sums
__device__ float  g_pden[JSPLIT * BB * NN];          // partial denominators

__device__ __forceinline__ float ex2f(float x) {
    float y; asm("ex2.approx.f32 %0, %1;" : "=f"(y) : "f"(x)); return y;
}
__device__ __forceinline__ float tanhf_hw(float x) {
    float y; asm("tanh.approx.f32 %0, %1;" : "=f"(y) : "f"(x)); return y;
}
// w = exp(tanh(s)) = ex2(tanh(s) * log2(e)).  2 MUFU + 1 MUL.
__device__ __forceinline__ float gat_w(float s) {
    return ex2f(tanhf_hw(s) * 1.4426950408889634f);
}
__device__ __forceinline__ float eluf(float x) { return x > 0.f ? x : expm1f(x); }
__device__ __forceinline__ uint32_t packh2(float lo, float hi) {
    __half2 h = __floats2half2_rn(lo, hi);
    return *(uint32_t*)&h;
}
__device__ __forceinline__ uint32_t smem_u32(const void* p) {
    uint32_t a;
    asm("{ .reg .u64 t; cvta.to.shared.u64 t, %1; cvt.u32.u64 %0, t; }"
        : "=r"(a) : "l"(p));
    return a;
}
__device__ __forceinline__ void cp16(uint32_t dst, const void* src) {
    asm volatile("cp.async.cg.shared.global [%0], [%1], 16;"
                 :: "r"(dst), "l"(src) : "memory");
}

// ---------------------------------------------------------------------------
// Kernel A: h = x@W (f32), f1/f2 = h@a halves, emit h^T fp16 [b][f][j].
// 1024 CTAs x 256 thr, 16 rows/CTA (warp owns 2 rows, lane owns feature pair).
// ---------------------------------------------------------------------------
#define HP 20   // hsT pitch in halves (40B rows)

__global__ __launch_bounds__(256) void k_proj(const float* __restrict__ x,
                                              const float* __restrict__ W,
                                              const float* __restrict__ a) {
    __shared__ float  Ws[FIN * FOUT];       // 32 KB
    __shared__ __half hsT[FOUT * HP];       // 2.5 KB

    const int tid  = threadIdx.x;
    const int lane = tid & 31;
    const int warp = tid >> 5;
    const int b    = blockIdx.x >> 7;              // 128 blocks per batch
    const int jb   = (blockIdx.x & 127) * 16;      // 16-row block

    {
        const float4* Wsrc = (const float4*)W;
        float4*       Wdst = (float4*)Ws;
#pragma unroll
        for (int c = 0; c < 8; ++c) Wdst[tid + 256 * c] = Wsrc[tid + 256 * c];
    }
    const float2 av1 = *(const float2*)(a + 2 * lane);
    const float2 av2 = *(const float2*)(a + FOUT + 2 * lane);
    __syncthreads();

    const float* xr = x + ((size_t)b * NN + jb + warp * 2) * FIN;
    float2 acc[2];
    acc[0] = make_float2(0.f, 0.f);
    acc[1] = make_float2(0.f, 0.f);

#pragma unroll 8
    for (int k4 = 0; k4 < FIN / 4; ++k4) {
        const float4 xv0 = __ldg((const float4*)xr + k4);
        const float4 xv1 = __ldg((const float4*)(xr + FIN) + k4);
#pragma unroll
        for (int kk = 0; kk < 4; ++kk) {
            const float2 wv = *(const float2*)&Ws[(k4 * 4 + kk) * FOUT + 2 * lane];
            const float x0 = (kk == 0) ? xv0.x : (kk == 1) ? xv0.y
                           : (kk == 2) ? xv0.z : xv0.w;
            const float x1 = (kk == 0) ? xv1.x : (kk == 1) ? xv1.y
                           : (kk == 2) ? xv1.z : xv1.w;
            acc[0].x = fmaf(x0, wv.x, acc[0].x);
            acc[0].y = fmaf(x0, wv.y, acc[0].y);
            acc[1].x = fmaf(x1, wv.x, acc[1].x);
            acc[1].y = fmaf(x1, wv.y, acc[1].y);
        }
    }

#pragma unroll
    for (int r = 0; r < 2; ++r) {
        const int rowloc = warp * 2 + r;
        hsT[(2 * lane) * HP + rowloc]     = __float2half_rn(acc[r].x);
        hsT[(2 * lane + 1) * HP + rowloc] = __float2half_rn(acc[r].y);
        float p1 = acc[r].x * av1.x + acc[r].y * av1.y;
        float p2 = acc[r].x * av2.x + acc[r].y * av2.y;
#pragma unroll
        for (int d = 16; d; d >>= 1) {
            p1 += __shfl_xor_sync(0xffffffffu, p1, d);
            p2 += __shfl_xor_sync(0xffffffffu, p2, d);
        }
        if (lane == 0) {
            g_f1[b * NN + jb + rowloc] = p1;
            g_f2[b * NN + jb + rowloc] = p2;
        }
    }
    __syncthreads();

    // 64 feats x 4 segs of 4 halves = 256 slots, one uint2 per thread
    {
        const int feat = tid >> 2;
        const int seg  = tid & 3;
        const uint2 v = *(const uint2*)&hsT[feat * HP + seg * 4];
        *(uint2*)(g_ht + ((size_t)(b * FOUT + feat)) * NN + jb + seg * 4) = v;
    }
}

// ---------------------------------------------------------------------------
// Kernel B: fused GAT attention on mma.sync.m16n8k16, j-split x8.
// Grid (16, 8, 8) = 1024 CTAs; 256 thr = 8 warps; warp owns 16 i x 64 f over
// a 256-j slice. h^T tiles double-buffered via cp.async. 4 CTAs/SM.
// ---------------------------------------------------------------------------
#define PITCH 72
#define NSTAGE (JLEN / 64)   // 4
#define NKS (JLEN / 16)      // 16

__global__ __launch_bounds__(256, 4) void k_attn(const int* __restrict__ adj) {
    __shared__ float  f2s[JLEN];                 // 1 KB
    __shared__ __half hTs[2][FOUT * PITCH];      // 2 x 9 KB

    const int tid   = threadIdx.x;
    const int warp  = tid >> 5;
    const int lane  = tid & 31;
    const int t     = lane & 3;
    const int g     = lane >> 2;
    const int b     = blockIdx.z;
    const int split = blockIdx.y;
    const int i0    = blockIdx.x * 128;
    const int jb    = split * JLEN;
    const int r0    = i0 + warp * 16 + g;
    const int r1    = r0 + 8;

    const float f1_0 = g_f1[b * NN + r0];
    const float f1_1 = g_f1[b * NN + r1];
    f2s[tid] = g_f2[b * NN + jb + tid];

    const int* arow0 = adj + ((size_t)b * NN + r0) * NN + jb;
    const int* arow1 = adj + ((size_t)b * NN + r1) * NN + jb;
    const __half* hb = g_ht + (size_t)b * FOUT * NN + jb;

    // cp.async slots: 64 feats x 8 segs of 8 halves = 512 -> 2 per thread
    const int f_a = tid >> 3, f_b = (tid + 256) >> 3;
    const int sg  = tid & 7;
    const uint32_t dA = smem_u32(&hTs[0][f_a * PITCH + sg * 8]);
    const uint32_t dB = smem_u32(&hTs[0][f_b * PITCH + sg * 8]);
    const uint32_t bufstep = (uint32_t)(FOUT * PITCH * 2);
    const __half* sA = hb + (size_t)f_a * NN + sg * 8;
    const __half* sB = hb + (size_t)f_b * NN + sg * 8;

    cp16(dA, sA);
    cp16(dB, sB);
    asm volatile("cp.async.commit_group;" ::: "memory");

    int2 pa0 = *(const int2*)(arow0 + 2 * t);
    int2 pa1 = *(const int2*)(arow0 + 8 + 2 * t);
    int2 pa2 = *(const int2*)(arow1 + 2 * t);
    int2 pa3 = *(const int2*)(arow1 + 8 + 2 * t);

    float acc[32];
#pragma unroll
    for (int k = 0; k < 32; ++k) acc[k] = 0.f;
    float ds0 = 0.f, ds1 = 0.f;

#pragma unroll
    for (int s = 0; s < NSTAGE; ++s) {
        if (s + 1 < NSTAGE) {
            const uint32_t db = ((s + 1) & 1) ? bufstep : 0u;
            cp16(dA + db, sA + (s + 1) * 64);
            cp16(dB + db, sB + (s + 1) * 64);
            asm volatile("cp.async.commit_group;" ::: "memory");
            asm volatile("cp.async.wait_group 1;" ::: "memory");
        } else {
            asm volatile("cp.async.wait_group 0;" ::: "memory");
        }
        __syncthreads();
        const __half* hcur = hTs[s & 1];

#pragma unroll
        for (int kk = 0; kk < 4; ++kk) {
            const int ks = s * 4 + kk;
            const int j0 = ks * 16;
            const int jn = (ks + 1 < NKS) ? (ks + 1) * 16 : 0;
            const int2 na0 = *(const int2*)(arow0 + jn + 2 * t);
            const int2 na1 = *(const int2*)(arow0 + jn + 8 + 2 * t);
            const int2 na2 = *(const int2*)(arow1 + jn + 2 * t);
            const int2 na3 = *(const int2*)(arow1 + jn + 8 + 2 * t);

            const float2 flo = *(const float2*)&f2s[j0 + 2 * t];
            const float2 fhi = *(const float2*)&f2s[j0 + 8 + 2 * t];

            float w00 = gat_w(f1_0 + flo.x), w01 = gat_w(f1_0 + flo.y);
            float w02 = gat_w(f1_0 + fhi.x), w03 = gat_w(f1_0 + fhi.y);
            float w10 = gat_w(f1_1 + flo.x), w11 = gat_w(f1_1 + flo.y);
            float w12 = gat_w(f1_1 + fhi.x), w13 = gat_w(f1_1 + fhi.y);
            w00 = pa0.x > 0 ? w00 : 0.f;  w01 = pa0.y > 0 ? w01 : 0.f;
            w02 = pa1.x > 0 ? w02 : 0.f;  w03 = pa1.y > 0 ? w03 : 0.f;
            w10 = pa2.x > 0 ? w10 : 0.f;  w11 = pa2.y > 0 ? w11 : 0.f;
            w12 = pa3.x > 0 ? w12 : 0.f;  w13 = pa3.y > 0 ? w13 : 0.f;
            ds0 += (w00 + w01) + (w02 + w03);
            ds1 += (w10 + w11) + (w12 + w13);

            const uint32_t A0 = packh2(w00, w01);
            const uint32_t A1 = packh2(w10, w11);
            const uint32_t A2 = packh2(w02, w03);
            const uint32_t A3 = packh2(w12, w13);

            const int ko = kk * 16 + 2 * t;
#pragma unroll
            for (int nb = 0; nb < 8; ++nb) {
                const __half* bp = hcur + (nb * 8 + g) * PITCH + ko;
                const uint32_t B0 = *(const uint32_t*)bp;
                const uint32_t B1 = *(const uint32_t*)(bp + 8);
                float* c = acc + nb * 4;
                asm volatile(
                    "mma.sync.aligned.m16n8k16.row.col.f32.f16.f16.f32 "
                    "{%0,%1,%2,%3}, {%4,%5,%6,%7}, {%8,%9}, {%0,%1,%2,%3};"
                    : "+f"(c[0]), "+f"(c[1]), "+f"(c[2]), "+f"(c[3])
                    : "r"(A0), "r"(A1), "r"(A2), "r"(A3), "r"(B0), "r"(B1));
            }
            pa0 = na0; pa1 = na1; pa2 = na2; pa3 = na3;
        }
        __syncthreads();
    }

    ds0 += __shfl_xor_sync(0xffffffffu, ds0, 1);
    ds0 += __shfl_xor_sync(0xffffffffu, ds0, 2);
    ds1 += __shfl_xor_sync(0xffffffffu, ds1, 1);
    ds1 += __shfl_xor_sync(0xffffffffu, ds1, 2);

    const size_t pbase = (size_t)(split * BB + b);
    if (t == 0) {
        g_pden[pbase * NN + r0] = ds0;
        g_pden[pbase * NN + r1] = ds1;
    }
    float* o0 = g_pout + (pbase * NN + r0) * FOUT;
    float* o1 = g_pout + (pbase * NN + r1) * FOUT;
#pragma unroll
    for (int nb = 0; nb < 8; ++nb) {
        *(float2*)(o0 + nb * 8 + 2 * t) = make_float2(acc[nb * 4 + 0], acc[nb * 4 + 1]);
        *(float2*)(o1 + nb * 8 + 2 * t) = make_float2(acc[nb * 4 + 2], acc[nb * 4 + 3]);
    }
}

// ---------------------------------------------------------------------------
// Kernel C: combine partials -> divide -> ELU -> out. Memory-bound.
// ---------------------------------------------------------------------------
__global__ __launch_bounds__(256) void k_comb(float* __restrict__ out) {
    const int idx = blockIdx.x * 256 + threadIdx.x;   // 0 .. BB*NN*16-1
    const int row = idx >> 4;
    const int seg = idx & 15;

    float den = 0.f;
#pragma unroll
    for (int s = 0; s < JSPLIT; ++s) den += g_pden[(size_t)s * BB * NN + row];
    const float inv = 1.0f / den;

    float4 v = make_float4(0.f, 0.f, 0.f, 0.f);
#pragma unroll
    for (int s = 0; s < JSPLIT; ++s) {
        const float4 p = *(const float4*)(g_pout +
            ((size_t)s * BB * NN + row) * FOUT + seg * 4);
        v.x += p.x; v.y += p.y; v.z += p.z; v.w += p.w;
    }
    v.x = eluf(v.x * inv); v.y = eluf(v.y * inv);
    v.z = eluf(v.z * inv); v.w = eluf(v.w * inv);
    *(float4*)(out + (size_t)row * FOUT + seg * 4) = v;
}

// ---------------------------------------------------------------------------
extern "C" void kernel_launch(void* const* d_in, const int* in_sizes, int n_in,
                              void* d_out, int out_size) {
    const float* x   = (const float*)d_in[0];
    const int*   adj = (const int*)d_in[1];
    const float* W   = (const float*)d_in[2];
    const float* a   = (const float*)d_in[3];
    float*       out = (float*)d_out;

    k_proj<<<BB * NN / 16, 256>>>(x, W, a);
    k_attn<<<dim3(16, JSPLIT, BB), 256>>>(adj);
    k_comb<<<BB * NN * 16 / 256, 256>>>(out);
}

// round 8
// speedup vs baseline: 3.6953x; 1.0568x over previous
#include <cuda_runtime.h>
#include <cuda_fp16.h>
#include <cstdint>

#define BB 8
#define NN 2048
#define FIN 128
#define FOUT 64
#define JSPLIT 8
#define JLEN (NN / JSPLIT)   // 256

// ---- scratch (static device arrays are allowed) ----
__device__ float  g_f1[BB * NN];
__device__ float  g_f2[BB * NN];
__device__ __half g_ht[BB * FOUT * NN];              // h^T fp16 [b][f][j]
__device__ float  g_pout[JSPLIT * BB * NN * FOUT];   // 32 MB partial PV sums
__device__ float  g_pden[JSPLIT * BB * NN];          // partial denominators

__device__ __forceinline__ float ex2f(float x) {
    float y; asm("ex2.approx.f32 %0, %1;" : "=f"(y) : "f"(x)); return y;
}
__device__ __forceinline__ float tanhf_hw(float x) {
    float y; asm("tanh.approx.f32 %0, %1;" : "=f"(y) : "f"(x)); return y;
}
// w = exp(tanh(s)) = ex2(tanh(s) * log2(e)).  2 MUFU + 1 MUL.
__device__ __forceinline__ float gat_w(float s) {
    return ex2f(tanhf_hw(s) * 1.4426950408889634f);
}
__device__ __forceinline__ float eluf(float x) { return x > 0.f ? x : expm1f(x); }
__device__ __forceinline__ uint32_t packh2(float lo, float hi) {
    __half2 h = __floats2half2_rn(lo, hi);
    return *(uint32_t*)&h;
}
__device__ __forceinline__ uint32_t smem_u32(const void* p) {
    uint32_t a;
    asm("{ .reg .u64 t; cvta.to.shared.u64 t, %1; cvt.u32.u64 %0, t; }"
        : "=r"(a) : "l"(p));
    return a;
}
__device__ __forceinline__ void cp16(uint32_t dst, const void* src) {
    asm volatile("cp.async.cg.shared.global [%0], [%1], 16;"
                 :: "r"(dst), "l"(src) : "memory");
}

// ---------------------------------------------------------------------------
// Kernel A: h = x@W (f32), f1/f2 = h@a halves, emit h^T fp16 [b][f][j].
// 512 CTAs x 256 thr, 32 rows/CTA. Warp owns 4 rows; lane t=lane&15 owns
// feature quad 4t..4t+3 (LDS.128, reused over 4 rows = 16 FFMA per LDS);
// half-warps (lane>>4) split the k dimension, merged by one xor-16 shuffle.
// ---------------------------------------------------------------------------
#define HP 40   // hsT pitch in halves

__global__ __launch_bounds__(256) void k_proj(const float* __restrict__ x,
                                              const float* __restrict__ W,
                                              const float* __restrict__ a) {
    __shared__ float  Ws[FIN * FOUT];       // 32 KB
    __shared__ __half hsT[FOUT * HP];       // 5 KB

    const int tid  = threadIdx.x;
    const int lane = tid & 31;
    const int warp = tid >> 5;
    const int t    = lane & 15;             // feature quad index
    const int hh   = lane >> 4;             // k-half 0/1
    const int b    = blockIdx.x >> 6;       // 64 blocks per batch
    const int jb   = (blockIdx.x & 63) * 32;

    {
        const float4* Wsrc = (const float4*)W;
        float4*       Wdst = (float4*)Ws;
#pragma unroll
        for (int c = 0; c < 8; ++c) Wdst[tid + 256 * c] = Wsrc[tid + 256 * c];
    }
    const float4 av1 = *(const float4*)(a + 4 * t);
    const float4 av2 = *(const float4*)(a + FOUT + 4 * t);
    __syncthreads();

    const float* xr = x + ((size_t)b * NN + jb + warp * 4) * FIN;
    float4 acc[4];
#pragma unroll
    for (int r = 0; r < 4; ++r) acc[r] = make_float4(0.f, 0.f, 0.f, 0.f);

    // half hh handles k = k4*4 + hh*2 + {0,1}
#pragma unroll 4
    for (int k4 = 0; k4 < FIN / 4; ++k4) {
        const int k0 = k4 * 4 + hh * 2;
        float2 xv[4];
#pragma unroll
        for (int r = 0; r < 4; ++r)
            xv[r] = __ldg((const float2*)(xr + (size_t)r * FIN + k0));
        const float4 w0 = *(const float4*)&Ws[k0 * FOUT + 4 * t];
        const float4 w1 = *(const float4*)&Ws[(k0 + 1) * FOUT + 4 * t];
#pragma unroll
        for (int r = 0; r < 4; ++r) {
            acc[r].x = fmaf(xv[r].x, w0.x, acc[r].x);
            acc[r].y = fmaf(xv[r].x, w0.y, acc[r].y);
            acc[r].z = fmaf(xv[r].x, w0.z, acc[r].z);
            acc[r].w = fmaf(xv[r].x, w0.w, acc[r].w);
            acc[r].x = fmaf(xv[r].y, w1.x, acc[r].x);
            acc[r].y = fmaf(xv[r].y, w1.y, acc[r].y);
            acc[r].z = fmaf(xv[r].y, w1.z, acc[r].z);
            acc[r].w = fmaf(xv[r].y, w1.w, acc[r].w);
        }
    }

    // merge the two k-halves (lanes l and l+16 hold complementary sums)
#pragma unroll
    for (int r = 0; r < 4; ++r) {
        acc[r].x += __shfl_xor_sync(0xffffffffu, acc[r].x, 16);
        acc[r].y += __shfl_xor_sync(0xffffffffu, acc[r].y, 16);
        acc[r].z += __shfl_xor_sync(0xffffffffu, acc[r].z, 16);
        acc[r].w += __shfl_xor_sync(0xffffffffu, acc[r].w, 16);
    }

#pragma unroll
    for (int r = 0; r < 4; ++r) {
        const int rowloc = warp * 4 + r;
        if (hh == 0) {
            hsT[(4 * t) * HP + rowloc]     = __float2half_rn(acc[r].x);
            hsT[(4 * t + 1) * HP + rowloc] = __float2half_rn(acc[r].y);
            hsT[(4 * t + 2) * HP + rowloc] = __float2half_rn(acc[r].z);
            hsT[(4 * t + 3) * HP + rowloc] = __float2half_rn(acc[r].w);
        }
        float p1 = acc[r].x * av1.x + acc[r].y * av1.y
                 + acc[r].z * av1.z + acc[r].w * av1.w;
        float p2 = acc[r].x * av2.x + acc[r].y * av2.y
                 + acc[r].z * av2.z + acc[r].w * av2.w;
#pragma unroll
        for (int d = 8; d; d >>= 1) {
            p1 += __shfl_xor_sync(0xffffffffu, p1, d);
            p2 += __shfl_xor_sync(0xffffffffu, p2, d);
        }
        if (lane == 0) {
            g_f1[b * NN + jb + rowloc] = p1;
            g_f2[b * NN + jb + rowloc] = p2;
        }
    }
    __syncthreads();

    // 64 feats x 4 segs of 8 halves = 256 slots, one uint4 per thread
    {
        const int feat = tid >> 2;
        const int seg  = tid & 3;
        const uint4 v = *(const uint4*)&hsT[feat * HP + seg * 8];
        *(uint4*)(g_ht + ((size_t)(b * FOUT + feat)) * NN + jb + seg * 8) = v;
    }
}

// ---------------------------------------------------------------------------
// Kernel B: fused GAT attention on mma.sync.m16n8k16, j-split x8.
// Grid (16, 8, 8) = 1024 CTAs; 256 thr = 8 warps; warp owns 16 i x 64 f over
// a 256-j slice. h^T tiles double-buffered via cp.async.
// (256,3): 85-reg cap so acc[32]+prefetch live in registers, no spills.
// ---------------------------------------------------------------------------
#define PITCH 72
#define NSTAGE (JLEN / 64)   // 4
#define NKS (JLEN / 16)      // 16

__global__ __launch_bounds__(256, 3) void k_attn(const int* __restrict__ adj) {
    __shared__ float  f2s[JLEN];                 // 1 KB
    __shared__ __half hTs[2][FOUT * PITCH];      // 2 x 9 KB

    const int tid   = threadIdx.x;
    const int warp  = tid >> 5;
    const int lane  = tid & 31;
    const int t     = lane & 3;
    const int g     = lane >> 2;
    const int b     = blockIdx.z;
    const int split = blockIdx.y;
    const int i0    = blockIdx.x * 128;
    const int jb    = split * JLEN;
    const int r0    = i0 + warp * 16 + g;
    const int r1    = r0 + 8;

    const float f1_0 = g_f1[b * NN + r0];
    const float f1_1 = g_f1[b * NN + r1];
    f2s[tid] = g_f2[b * NN + jb + tid];

    const int* arow0 = adj + ((size_t)b * NN + r0) * NN + jb;
    const int* arow1 = adj + ((size_t)b * NN + r1) * NN + jb;
    const __half* hb = g_ht + (size_t)b * FOUT * NN + jb;

    // cp.async slots: 64 feats x 8 segs of 8 halves = 512 -> 2 per thread
    const int f_a = tid >> 3, f_b = (tid + 256) >> 3;
    const int sg  = tid & 7;
    const uint32_t dA = smem_u32(&hTs[0][f_a * PITCH + sg * 8]);
    const uint32_t dB = smem_u32(&hTs[0][f_b * PITCH + sg * 8]);
    const uint32_t bufstep = (uint32_t)(FOUT * PITCH * 2);
    const __half* sA = hb + (size_t)f_a * NN + sg * 8;
    const __half* sB = hb + (size_t)f_b * NN + sg * 8;

    cp16(dA, sA);
    cp16(dB, sB);
    asm volatile("cp.async.commit_group;" ::: "memory");

    int2 pa0 = *(const int2*)(arow0 + 2 * t);
    int2 pa1 = *(const int2*)(arow0 + 8 + 2 * t);
    int2 pa2 = *(const int2*)(arow1 + 2 * t);
    int2 pa3 = *(const int2*)(arow1 + 8 + 2 * t);

    float acc[32];
#pragma unroll
    for (int k = 0; k < 32; ++k) acc[k] = 0.f;
    float ds0 = 0.f, ds1 = 0.f;

#pragma unroll
    for (int s = 0; s < NSTAGE; ++s) {
        if (s + 1 < NSTAGE) {
            const uint32_t db = ((s + 1) & 1) ? bufstep : 0u;
            cp16(dA + db, sA + (s + 1) * 64);
            cp16(dB + db, sB + (s + 1) * 64);
            asm volatile("cp.async.commit_group;" ::: "memory");
            asm volatile("cp.async.wait_group 1;" ::: "memory");
        } else {
            asm volatile("cp.async.wait_group 0;" ::: "memory");
        }
        __syncthreads();
        const __half* hcur = hTs[s & 1];

#pragma unroll
        for (int kk = 0; kk < 4; ++kk) {
            const int ks = s * 4 + kk;
            const int j0 = ks * 16;
            const int jn = (ks + 1 < NKS) ? (ks + 1) * 16 : 0;
            const int2 na0 = *(const int2*)(arow0 + jn + 2 * t);
            const int2 na1 = *(const int2*)(arow0 + jn + 8 + 2 * t);
            const int2 na2 = *(const int2*)(arow1 + jn + 2 * t);
            const int2 na3 = *(const int2*)(arow1 + jn + 8 + 2 * t);

            const float2 flo = *(const float2*)&f2s[j0 + 2 * t];
            const float2 fhi = *(const float2*)&f2s[j0 + 8 + 2 * t];

            float w00 = gat_w(f1_0 + flo.x), w01 = gat_w(f1_0 + flo.y);
            float w02 = gat_w(f1_0 + fhi.x), w03 = gat_w(f1_0 + fhi.y);
            float w10 = gat_w(f1_1 + flo.x), w11 = gat_w(f1_1 + flo.y);
            float w12 = gat_w(f1_1 + fhi.x), w13 = gat_w(f1_1 + fhi.y);
            w00 = pa0.x > 0 ? w00 : 0.f;  w01 = pa0.y > 0 ? w01 : 0.f;
            w02 = pa1.x > 0 ? w02 : 0.f;  w03 = pa1.y > 0 ? w03 : 0.f;
            w10 = pa2.x > 0 ? w10 : 0.f;  w11 = pa2.y > 0 ? w11 : 0.f;
            w12 = pa3.x > 0 ? w12 : 0.f;  w13 = pa3.y > 0 ? w13 : 0.f;
            ds0 += (w00 + w01) + (w02 + w03);
            ds1 += (w10 + w11) + (w12 + w13);

            const uint32_t A0 = packh2(w00, w01);
            const uint32_t A1 = packh2(w10, w11);
            const uint32_t A2 = packh2(w02, w03);
            const uint32_t A3 = packh2(w12, w13);

            const int ko = kk * 16 + 2 * t;
#pragma unroll
            for (int nb = 0; nb < 8; ++nb) {
                const __half* bp = hcur + (nb * 8 + g) * PITCH + ko;
                const uint32_t B0 = *(const uint32_t*)bp;
                const uint32_t B1 = *(const uint32_t*)(bp + 8);
                float* c = acc + nb * 4;
                asm volatile(
                    "mma.sync.aligned.m16n8k16.row.col.f32.f16.f16.f32 "
                    "{%0,%1,%2,%3}, {%4,%5,%6,%7}, {%8,%9}, {%0,%1,%2,%3};"
                    : "+f"(c[0]), "+f"(c[1]), "+f"(c[2]), "+f"(c[3])
                    : "r"(A0), "r"(A1), "r"(A2), "r"(A3), "r"(B0), "r"(B1));
            }
            pa0 = na0; pa1 = na1; pa2 = na2; pa3 = na3;
        }
        __syncthreads();
    }

    ds0 += __shfl_xor_sync(0xffffffffu, ds0, 1);
    ds0 += __shfl_xor_sync(0xffffffffu, ds0, 2);
    ds1 += __shfl_xor_sync(0xffffffffu, ds1, 1);
    ds1 += __shfl_xor_sync(0xffffffffu, ds1, 2);

    const size_t pbase = (size_t)(split * BB + b);
    if (t == 0) {
        g_pden[pbase * NN + r0] = ds0;
        g_pden[pbase * NN + r1] = ds1;
    }
    float* o0 = g_pout + (pbase * NN + r0) * FOUT;
    float* o1 = g_pout + (pbase * NN + r1) * FOUT;
#pragma unroll
    for (int nb = 0; nb < 8; ++nb) {
        *(float2*)(o0 + nb * 8 + 2 * t) = make_float2(acc[nb * 4 + 0], acc[nb * 4 + 1]);
        *(float2*)(o1 + nb * 8 + 2 * t) = make_float2(acc[nb * 4 + 2], acc[nb * 4 + 3]);
    }
}

// ---------------------------------------------------------------------------
// Kernel C: combine partials -> divide -> ELU -> out. Memory-bound.
// ---------------------------------------------------------------------------
__global__ __launch_bounds__(256) void k_comb(float* __restrict__ out) {
    const int idx = blockIdx.x * 256 + threadIdx.x;   // 0 .. BB*NN*16-1
    const int row = idx >> 4;
    const int seg = idx & 15;

    float den = 0.f;
#pragma unroll
    for (int s = 0; s < JSPLIT; ++s) den += g_pden[(size_t)s * BB * NN + row];
    const float inv = 1.0f / den;

    float4 v = make_float4(0.f, 0.f, 0.f, 0.f);
#pragma unroll
    for (int s = 0; s < JSPLIT; ++s) {
        const float4 p = *(const float4*)(g_pout +
            ((size_t)s * BB * NN + row) * FOUT + seg * 4);
        v.x += p.x; v.y += p.y; v.z += p.z; v.w += p.w;
    }
    v.x = eluf(v.x * inv); v.y = eluf(v.y * inv);
    v.z = eluf(v.z * inv); v.w = eluf(v.w * inv);
    *(float4*)(out + (size_t)row * FOUT + seg * 4) = v;
}

// ---------------------------------------------------------------------------
extern "C" void kernel_launch(void* const* d_in, const int* in_sizes, int n_in,
                              void* d_out, int out_size) {
    const float* x   = (const float*)d_in[0];
    const int*   adj = (const int*)d_in[1];
    const float* W   = (const float*)d_in[2];
    const float* a   = (const float*)d_in[3];
    float*       out = (float*)d_out;

    k_proj<<<BB * NN / 32, 256>>>(x, W, a);
    k_attn<<<dim3(16, JSPLIT, BB), 256>>>(adj);
    k_comb<<<BB * NN * 16 / 256, 256>>>(out);
}

// round 9
// speedup vs baseline: 3.7251x; 1.0080x over previous
#include <cuda_runtime.h>
#include <cuda_fp16.h>
#include <cstdint>

#define BB 8
#define NN 2048
#define FIN 128
#define FOUT 64
#define JSPLIT 8
#define JLEN (NN / JSPLIT)   // 256

// ---- scratch (static device arrays are allowed) ----
__device__ float  g_f1[BB * NN];
__device__ float  g_f2[BB * NN];
__device__ __half g_ht[BB * FOUT * NN];              // h^T fp16 [b][f][j]
__device__ float  g_pout[JSPLIT * BB * NN * FOUT];   // 32 MB partial PV sums
__device__ float  g_pden[JSPLIT * BB * NN];          // partial denominators

__device__ __forceinline__ float ex2f(float x) {
    float y; asm("ex2.approx.f32 %0, %1;" : "=f"(y) : "f"(x)); return y;
}
__device__ __forceinline__ float tanhf_hw(float x) {
    float y; asm("tanh.approx.f32 %0, %1;" : "=f"(y) : "f"(x)); return y;
}
// w = exp(tanh(s)) = ex2(tanh(s) * log2(e)).  2 MUFU + 1 MUL.
__device__ __forceinline__ float gat_w(float s) {
    return ex2f(tanhf_hw(s) * 1.4426950408889634f);
}
__device__ __forceinline__ float eluf(float x) { return x > 0.f ? x : expm1f(x); }
__device__ __forceinline__ uint32_t packh2(float lo, float hi) {
    __half2 h = __floats2half2_rn(lo, hi);
    return *(uint32_t*)&h;
}
__device__ __forceinline__ uint32_t smem_u32(const void* p) {
    uint32_t a;
    asm("{ .reg .u64 t; cvta.to.shared.u64 t, %1; cvt.u32.u64 %0, t; }"
        : "=r"(a) : "l"(p));
    return a;
}
__device__ __forceinline__ void cp16(uint32_t dst, const void* src) {
    asm volatile("cp.async.cg.shared.global [%0], [%1], 16;"
                 :: "r"(dst), "l"(src) : "memory");
}

// ---------------------------------------------------------------------------
// Kernel A: h = x@W (f32), f1/f2 = h@a halves, emit h^T fp16 [b][f][j].
// 512 CTAs x 256 thr, 32 rows/CTA. Warp owns 4 rows; lane t=lane&15 owns
// feature quad 4t..4t+3; half-warps split k, merged by one xor-16 shuffle.
// ---------------------------------------------------------------------------
#define HP 40   // hsT pitch in halves

__global__ __launch_bounds__(256) void k_proj(const float* __restrict__ x,
                                              const float* __restrict__ W,
                                              const float* __restrict__ a) {
    __shared__ float  Ws[FIN * FOUT];       // 32 KB
    __shared__ __half hsT[FOUT * HP];       // 5 KB

    const int tid  = threadIdx.x;
    const int lane = tid & 31;
    const int warp = tid >> 5;
    const int t    = lane & 15;
    const int hh   = lane >> 4;
    const int b    = blockIdx.x >> 6;
    const int jb   = (blockIdx.x & 63) * 32;

    {
        const float4* Wsrc = (const float4*)W;
        float4*       Wdst = (float4*)Ws;
#pragma unroll
        for (int c = 0; c < 8; ++c) Wdst[tid + 256 * c] = Wsrc[tid + 256 * c];
    }
    const float4 av1 = *(const float4*)(a + 4 * t);
    const float4 av2 = *(const float4*)(a + FOUT + 4 * t);
    __syncthreads();

    const float* xr = x + ((size_t)b * NN + jb + warp * 4) * FIN;
    float4 acc[4];
#pragma unroll
    for (int r = 0; r < 4; ++r) acc[r] = make_float4(0.f, 0.f, 0.f, 0.f);

#pragma unroll 4
    for (int k4 = 0; k4 < FIN / 4; ++k4) {
        const int k0 = k4 * 4 + hh * 2;
        float2 xv[4];
#pragma unroll
        for (int r = 0; r < 4; ++r)
            xv[r] = __ldg((const float2*)(xr + (size_t)r * FIN + k0));
        const float4 w0 = *(const float4*)&Ws[k0 * FOUT + 4 * t];
        const float4 w1 = *(const float4*)&Ws[(k0 + 1) * FOUT + 4 * t];
#pragma unroll
        for (int r = 0; r < 4; ++r) {
            acc[r].x = fmaf(xv[r].x, w0.x, acc[r].x);
            acc[r].y = fmaf(xv[r].x, w0.y, acc[r].y);
            acc[r].z = fmaf(xv[r].x, w0.z, acc[r].z);
            acc[r].w = fmaf(xv[r].x, w0.w, acc[r].w);
            acc[r].x = fmaf(xv[r].y, w1.x, acc[r].x);
            acc[r].y = fmaf(xv[r].y, w1.y, acc[r].y);
            acc[r].z = fmaf(xv[r].y, w1.z, acc[r].z);
            acc[r].w = fmaf(xv[r].y, w1.w, acc[r].w);
        }
    }

#pragma unroll
    for (int r = 0; r < 4; ++r) {
        acc[r].x += __shfl_xor_sync(0xffffffffu, acc[r].x, 16);
        acc[r].y += __shfl_xor_sync(0xffffffffu, acc[r].y, 16);
        acc[r].z += __shfl_xor_sync(0xffffffffu, acc[r].z, 16);
        acc[r].w += __shfl_xor_sync(0xffffffffu, acc[r].w, 16);
    }

#pragma unroll
    for (int r = 0; r < 4; ++r) {
        const int rowloc = warp * 4 + r;
        if (hh == 0) {
            hsT[(4 * t) * HP + rowloc]     = __float2half_rn(acc[r].x);
            hsT[(4 * t + 1) * HP + rowloc] = __float2half_rn(acc[r].y);
            hsT[(4 * t + 2) * HP + rowloc] = __float2half_rn(acc[r].z);
            hsT[(4 * t + 3) * HP + rowloc] = __float2half_rn(acc[r].w);
        }
        float p1 = acc[r].x * av1.x + acc[r].y * av1.y
                 + acc[r].z * av1.z + acc[r].w * av1.w;
        float p2 = acc[r].x * av2.x + acc[r].y * av2.y
                 + acc[r].z * av2.z + acc[r].w * av2.w;
#pragma unroll
        for (int d = 8; d; d >>= 1) {
            p1 += __shfl_xor_sync(0xffffffffu, p1, d);
            p2 += __shfl_xor_sync(0xffffffffu, p2, d);
        }
        if (lane == 0) {
            g_f1[b * NN + jb + rowloc] = p1;
            g_f2[b * NN + jb + rowloc] = p2;
        }
    }
    __syncthreads();

    {
        const int feat = tid >> 2;
        const int seg  = tid & 3;
        const uint4 v = *(const uint4*)&hsT[feat * HP + seg * 8];
        *(uint4*)(g_ht + ((size_t)(b * FOUT + feat)) * NN + jb + seg * 8) = v;
    }
}

// ---------------------------------------------------------------------------
// Kernel B: fused GAT attention on mma.sync.m16n8k16, j-split x8.
// Grid (16, 8, 8) = 1024 CTAs; 256 thr = 8 warps; warp owns 16 i x 64 f over
// a 256-j slice, processed as 8 stages of 32 j. BOTH the h^T tile and the
// adjacency tile are cp.async-staged per stage (double buffered) -> no
// in-loop LDG, no prefetch registers; fits 64 regs for 4 CTAs/SM.
// ---------------------------------------------------------------------------
#define HPITCH 40            // halves per h-tile row (80 B, 16B-aligned)
#define APITCH 36            // ints per adj-tile row (144 B, 16B-aligned)
#define NST (JLEN / 32)      // 8 stages

__global__ __launch_bounds__(256, 4) void k_attn(const int* __restrict__ adj) {
    __shared__ float                  f2s[JLEN];                // 1 KB
    __shared__ __align__(16) __half   hTs[2][FOUT * HPITCH];    // 10 KB
    __shared__ __align__(16) int      ajs[2][128 * APITCH];     // 36 KB

    const int tid   = threadIdx.x;
    const int warp  = tid >> 5;
    const int lane  = tid & 31;
    const int t     = lane & 3;
    const int g     = lane >> 2;
    const int b     = blockIdx.z;
    const int split = blockIdx.y;
    const int i0    = blockIdx.x * 128;
    const int jb    = split * JLEN;

    const int rloc0 = warp * 16 + g;       // local i-row (0..127)
    const int r0    = i0 + rloc0;
    const int r1    = r0 + 8;

    const float f1_0 = g_f1[b * NN + r0];
    const float f1_1 = g_f1[b * NN + r1];
    f2s[tid] = g_f2[b * NN + jb + tid];

    // ---- cp.async source/dst precomputation ----
    // h tile: 64 feats x 32 j = 256 x 16B chunks, 1 per thread
    const int hf = tid >> 2, hc = tid & 2 ? (tid & 3) : (tid & 3); // hc = tid&3
    const __half* hsrc = g_ht + (size_t)b * FOUT * NN + (size_t)hf * NN + jb + (tid & 3) * 8;
    const uint32_t hdst = smem_u32(&hTs[0][hf * HPITCH + (tid & 3) * 8]);
    // adj tile: 128 rows x 32 ints = 1024 x 16B chunks, 4 per thread
    // thread covers half a row: row = tid>>1, 64B at (tid&1)*64
    const int arow = tid >> 1;
    const int ahalf = (tid & 1) * 16;      // int offset within row
    const int* asrc = adj + ((size_t)b * NN + i0 + arow) * NN + jb + ahalf;
    const uint32_t adst = smem_u32(&ajs[0][arow * APITCH + ahalf]);

    const uint32_t hbuf = (uint32_t)(FOUT * HPITCH * 2);   // bytes per h buffer
    const uint32_t abuf = (uint32_t)(128 * APITCH * 4);    // bytes per adj buffer

    // prologue: stage 0
    cp16(hdst, hsrc);
#pragma unroll
    for (int q = 0; q < 4; ++q) cp16(adst + q * 16, asrc + q * 4);
    asm volatile("cp.async.commit_group;" ::: "memory");

    float acc[32];
#pragma unroll
    for (int k = 0; k < 32; ++k) acc[k] = 0.f;
    float ds0 = 0.f, ds1 = 0.f;

    for (int s = 0; s < NST; ++s) {
        if (s + 1 < NST) {
            const uint32_t hb2 = ((s + 1) & 1) ? hbuf : 0u;
            const uint32_t ab2 = ((s + 1) & 1) ? abuf : 0u;
            cp16(hdst + hb2, hsrc + (s + 1) * 32);
#pragma unroll
            for (int q = 0; q < 4; ++q)
                cp16(adst + ab2 + q * 16, asrc + (s + 1) * 32 + q * 4);
            asm volatile("cp.async.commit_group;" ::: "memory");
            asm volatile("cp.async.wait_group 1;" ::: "memory");
        } else {
            asm volatile("cp.async.wait_group 0;" ::: "memory");
        }
        __syncthreads();
        const __half* hcur = hTs[s & 1];
        const int*    acur = ajs[s & 1];

#pragma unroll
        for (int kk = 0; kk < 2; ++kk) {
            const int j0 = s * 32 + kk * 16;
            // adjacency from smem (2-way conflicts at worst)
            const int2 la0 = *(const int2*)&acur[rloc0 * APITCH + kk * 16 + 2 * t];
            const int2 la1 = *(const int2*)&acur[rloc0 * APITCH + kk * 16 + 8 + 2 * t];
            const int2 la2 = *(const int2*)&acur[(rloc0 + 8) * APITCH + kk * 16 + 2 * t];
            const int2 la3 = *(const int2*)&acur[(rloc0 + 8) * APITCH + kk * 16 + 8 + 2 * t];

            const float2 flo = *(const float2*)&f2s[j0 + 2 * t];
            const float2 fhi = *(const float2*)&f2s[j0 + 8 + 2 * t];

            float w00 = gat_w(f1_0 + flo.x), w01 = gat_w(f1_0 + flo.y);
            float w02 = gat_w(f1_0 + fhi.x), w03 = gat_w(f1_0 + fhi.y);
            float w10 = gat_w(f1_1 + flo.x), w11 = gat_w(f1_1 + flo.y);
            float w12 = gat_w(f1_1 + fhi.x), w13 = gat_w(f1_1 + fhi.y);
            w00 = la0.x > 0 ? w00 : 0.f;  w01 = la0.y > 0 ? w01 : 0.f;
            w02 = la1.x > 0 ? w02 : 0.f;  w03 = la1.y > 0 ? w03 : 0.f;
            w10 = la2.x > 0 ? w10 : 0.f;  w11 = la2.y > 0 ? w11 : 0.f;
            w12 = la3.x > 0 ? w12 : 0.f;  w13 = la3.y > 0 ? w13 : 0.f;
            ds0 += (w00 + w01) + (w02 + w03);
            ds1 += (w10 + w11) + (w12 + w13);

            const uint32_t A0 = packh2(w00, w01);
            const uint32_t A1 = packh2(w10, w11);
            const uint32_t A2 = packh2(w02, w03);
            const uint32_t A3 = packh2(w12, w13);

            const int ko = kk * 16 + 2 * t;
#pragma unroll
            for (int nb = 0; nb < 8; ++nb) {
                const __half* bp = hcur + (nb * 8 + g) * HPITCH + ko;
                const uint32_t B0 = *(const uint32_t*)bp;
                const uint32_t B1 = *(const uint32_t*)(bp + 8);
                float* c = acc + nb * 4;
                asm volatile(
                    "mma.sync.aligned.m16n8k16.row.col.f32.f16.f16.f32 "
                    "{%0,%1,%2,%3}, {%4,%5,%6,%7}, {%8,%9}, {%0,%1,%2,%3};"
                    : "+f"(c[0]), "+f"(c[1]), "+f"(c[2]), "+f"(c[3])
                    : "r"(A0), "r"(A1), "r"(A2), "r"(A3), "r"(B0), "r"(B1));
            }
        }
        __syncthreads();
    }

    ds0 += __shfl_xor_sync(0xffffffffu, ds0, 1);
    ds0 += __shfl_xor_sync(0xffffffffu, ds0, 2);
    ds1 += __shfl_xor_sync(0xffffffffu, ds1, 1);
    ds1 += __shfl_xor_sync(0xffffffffu, ds1, 2);

    const size_t pbase = (size_t)(split * BB + b);
    if (t == 0) {
        g_pden[pbase * NN + r0] = ds0;
        g_pden[pbase * NN + r1] = ds1;
    }
    float* o0 = g_pout + (pbase * NN + r0) * FOUT;
    float* o1 = g_pout + (pbase * NN + r1) * FOUT;
#pragma unroll
    for (int nb = 0; nb < 8; ++nb) {
        *(float2*)(o0 + nb * 8 + 2 * t) = make_float2(acc[nb * 4 + 0], acc[nb * 4 + 1]);
        *(float2*)(o1 + nb * 8 + 2 * t) = make_float2(acc[nb * 4 + 2], acc[nb * 4 + 3]);
    }
}

// ---------------------------------------------------------------------------
// Kernel C: combine partials -> divide -> ELU -> out. Memory-bound.
// ---------------------------------------------------------------------------
__global__ __launch_bounds__(256) void k_comb(float* __restrict__ out) {
    const int idx = blockIdx.x * 256 + threadIdx.x;
    const int row = idx >> 4;
    const int seg = idx & 15;

    float den = 0.f;
#pragma unroll
    for (int s = 0; s < JSPLIT; ++s) den += g_pden[(size_t)s * BB * NN + row];
    const float inv = 1.0f / den;

    float4 v = make_float4(0.f, 0.f, 0.f, 0.f);
#pragma unroll
    for (int s = 0; s < JSPLIT; ++s) {
        const float4 p = *(const float4*)(g_pout +
            ((size_t)s * BB * NN + row) * FOUT + seg * 4);
        v.x += p.x; v.y += p.y; v.z += p.z; v.w += p.w;
    }
    v.x = eluf(v.x * inv); v.y = eluf(v.y * inv);
    v.z = eluf(v.z * inv); v.w = eluf(v.w * inv);
    *(float4*)(out + (size_t)row * FOUT + seg * 4) = v;
}

// ---------------------------------------------------------------------------
extern "C" void kernel_launch(void* const* d_in, const int* in_sizes, int n_in,
                              void* d_out, int out_size) {
    const float* x   = (const float*)d_in[0];
    const int*   adj = (const int*)d_in[1];
    const float* W   = (const float*)d_in[2];
    const float* a   = (const float*)d_in[3];
    float*       out = (float*)d_out;

    k_proj<<<BB * NN / 32, 256>>>(x, W, a);
    k_attn<<<dim3(16, JSPLIT, BB), 256>>>(adj);
    k_comb<<<BB * NN * 16 / 256, 256>>>(out);
}